// round 5
// baseline (speedup 1.0000x reference)
#include <cuda_runtime.h>
#include <math_constants.h>

// DiceEmbedding fused single kernel:
//   out[n,e] = sum_d polar(v_n)[d] * (W@Q)[e,d] + b[e]
//   theta = log(0.01+|v|)/85*pi ; s=sin, c=cos
//   polar[j] = s^j * c (j=0..8), polar[9] = s^10
//
// R5: target 4 CTAs/SM (<=64 regs) for 32 warps/SM of store MLP.
// spolar chunks loaded via explicit ld.shared.v2.u64 and consumed
// immediately so only 4 temp regs stay live instead of 20.

#define EMB 1024
#define DPOL 10
#define RPB 256   // rows per block

__device__ __forceinline__ unsigned long long fma2(unsigned long long a,
                                                   unsigned long long b,
                                                   unsigned long long c) {
    unsigned long long d;
    asm("fma.rn.f32x2 %0, %1, %2, %3;" : "=l"(d) : "l"(a), "l"(b), "l"(c));
    return d;
}

__device__ __forceinline__ unsigned long long pack_dup(float x) {
    unsigned long long r;
    unsigned int u = __float_as_uint(x);
    asm("mov.b64 %0, {%1, %1};" : "=l"(r) : "r"(u));
    return r;
}

__device__ __forceinline__ unsigned long long pack2(float lo, float hi) {
    unsigned long long r;
    asm("mov.b64 %0, {%1, %2};" : "=l"(r) : "r"(__float_as_uint(lo)), "r"(__float_as_uint(hi)));
    return r;
}

__device__ __forceinline__ void unpack2(unsigned long long v, float& lo, float& hi) {
    unsigned int a, b;
    asm("mov.b64 {%0, %1}, %2;" : "=r"(a), "=r"(b) : "l"(v));
    lo = __uint_as_float(a);
    hi = __uint_as_float(b);
}

__device__ __forceinline__ void lds_v2u64(unsigned int saddr,
                                          unsigned long long& x,
                                          unsigned long long& y) {
    asm volatile("ld.shared.v2.u64 {%0, %1}, [%2];"
                 : "=l"(x), "=l"(y) : "r"(saddr));
}

__global__ void __launch_bounds__(256, 4)
dice_fused_kernel(const float* __restrict__ bv,
                  const float* __restrict__ Qm,    // [10,10]
                  const float* __restrict__ W,     // [1024,10]
                  const float* __restrict__ bias,  // [1024]
                  float* __restrict__ out,
                  int N) {
    // polar values duplicated into both f32x2 lanes, [row][d]
    __shared__ __align__(16) unsigned long long spolar[RPB][DPOL];
    __shared__ float sQ[DPOL * DPOL];

    const int t = threadIdx.x;
    const int rowBase = blockIdx.x * RPB;

    // stage Q for broadcast
    if (t < DPOL * DPOL) sQ[t] = Qm[t];
    __syncthreads();   // sQ ready

    // ---- phase 1: each thread computes polar for one row, writes smem ----
    {
        int r = rowBase + t;
        float v = (r < N) ? bv[r] : 0.f;
        const float k = (float)(CUDART_PI / 85.0);
        float theta = __logf(0.01f + fabsf(v)) * k;
        float s, c;
        __sincosf(theta, &s, &c);
        float p = c;
#pragma unroll
        for (int j = 0; j < 9; j++) {
            spolar[t][j] = pack_dup(p);
            p *= s;
        }
        float s2 = s * s;
        float s4 = s2 * s2;
        float s8 = s4 * s4;
        spolar[t][9] = pack_dup(s8 * s2);   // polar[9] = s^10
    }

    // ---- fold WQ for this thread's 4 output columns (independent of
    //      spolar; overlaps other warps reaching the barrier) ----
    const int c0 = t * 4;
    unsigned long long wqa[DPOL], wqb[DPOL];
    {
        float d0[DPOL], d1[DPOL];
#pragma unroll
        for (int d = 0; d < DPOL; d++) { d0[d] = 0.f; d1[d] = 0.f; }
#pragma unroll
        for (int k = 0; k < DPOL; k++) {
            float w0 = W[(c0 + 0) * DPOL + k];
            float w1 = W[(c0 + 1) * DPOL + k];
#pragma unroll
            for (int d = 0; d < DPOL; d++) {
                float q = sQ[k * DPOL + d];
                d0[d] = fmaf(w0, q, d0[d]);
                d1[d] = fmaf(w1, q, d1[d]);
            }
        }
#pragma unroll
        for (int d = 0; d < DPOL; d++) wqa[d] = pack2(d0[d], d1[d]);
#pragma unroll
        for (int d = 0; d < DPOL; d++) { d0[d] = 0.f; d1[d] = 0.f; }
#pragma unroll
        for (int k = 0; k < DPOL; k++) {
            float w2 = W[(c0 + 2) * DPOL + k];
            float w3 = W[(c0 + 3) * DPOL + k];
#pragma unroll
            for (int d = 0; d < DPOL; d++) {
                float q = sQ[k * DPOL + d];
                d0[d] = fmaf(w2, q, d0[d]);
                d1[d] = fmaf(w3, q, d1[d]);
            }
        }
#pragma unroll
        for (int d = 0; d < DPOL; d++) wqb[d] = pack2(d0[d], d1[d]);
    }

    ulonglong2 b2 = *reinterpret_cast<const ulonglong2*>(&bias[c0]);
    const unsigned long long ba = b2.x, bb = b2.y;

    __syncthreads();   // spolar ready

    const int nr = min(RPB, N - rowBase);
    float4* outp = reinterpret_cast<float4*>(out) + (size_t)rowBase * (EMB / 4) + t;

    // shared address of spolar[0][0]
    unsigned int sbase = (unsigned int)__cvta_generic_to_shared(&spolar[0][0]);

    // ---- phase 2: each row, every thread emits 4 contiguous fp32 outputs ----
    for (int r = 0; r < nr; r++) {
        unsigned int sa = sbase + r * (DPOL * 8);
        unsigned long long x, y;
        unsigned long long a = ba, b = bb;

        lds_v2u64(sa +  0, x, y);              // d0, d1
        a = fma2(x, wqa[0], a);  b = fma2(x, wqb[0], b);
        a = fma2(y, wqa[1], a);  b = fma2(y, wqb[1], b);
        lds_v2u64(sa + 16, x, y);              // d2, d3
        a = fma2(x, wqa[2], a);  b = fma2(x, wqb[2], b);
        a = fma2(y, wqa[3], a);  b = fma2(y, wqb[3], b);
        lds_v2u64(sa + 32, x, y);              // d4, d5
        a = fma2(x, wqa[4], a);  b = fma2(x, wqb[4], b);
        a = fma2(y, wqa[5], a);  b = fma2(y, wqb[5], b);
        lds_v2u64(sa + 48, x, y);              // d6, d7
        a = fma2(x, wqa[6], a);  b = fma2(x, wqb[6], b);
        a = fma2(y, wqa[7], a);  b = fma2(y, wqb[7], b);
        lds_v2u64(sa + 64, x, y);              // d8, d9
        a = fma2(x, wqa[8], a);  b = fma2(x, wqb[8], b);
        a = fma2(y, wqa[9], a);  b = fma2(y, wqb[9], b);

        float4 o;
        unpack2(a, o.x, o.y);
        unpack2(b, o.z, o.w);
        *outp = o;
        outp += EMB / 4;
    }
}

extern "C" void kernel_launch(void* const* d_in, const int* in_sizes, int n_in,
                              void* d_out, int out_size) {
    const float* bv = (const float*)d_in[0];   // [N]
    const float* Q  = (const float*)d_in[1];   // [10,10]
    const float* W  = (const float*)d_in[2];   // [1024,10]
    const float* b  = (const float*)d_in[3];   // [1024]
    float* out = (float*)d_out;
    const int N = in_sizes[0];

    int nblocks = (N + RPB - 1) / RPB;
    dice_fused_kernel<<<nblocks, 256>>>(bv, Q, W, b, out, N);
}

// round 6
// speedup vs baseline: 1.0006x; 1.0006x over previous
#include <cuda_runtime.h>
#include <math_constants.h>

// DiceEmbedding fused single kernel:
//   out[n,e] = sum_d polar(v_n)[d] * (W@Q)[e,d] + b[e]
//   theta = log(0.01+|v|)/85*pi ; s=sin, c=cos
//   polar[j] = s^j * c (j=0..8), polar[9] = s^10
//
// R6: R4 structure (batched loop-top LDS for MLP — R5 proved sequential
// consumption serializes; occupancy is not the lever). Prologue reordered:
// bv LDG issued before the sQ barrier so DRAM latency hides under the
// barrier + WQ fold.

#define EMB 1024
#define DPOL 10
#define RPB 256   // rows per block

__device__ __forceinline__ unsigned long long fma2(unsigned long long a,
                                                   unsigned long long b,
                                                   unsigned long long c) {
    unsigned long long d;
    asm("fma.rn.f32x2 %0, %1, %2, %3;" : "=l"(d) : "l"(a), "l"(b), "l"(c));
    return d;
}

__device__ __forceinline__ unsigned long long pack_dup(float x) {
    unsigned long long r;
    unsigned int u = __float_as_uint(x);
    asm("mov.b64 %0, {%1, %1};" : "=l"(r) : "r"(u));
    return r;
}

__device__ __forceinline__ unsigned long long pack2(float lo, float hi) {
    unsigned long long r;
    asm("mov.b64 %0, {%1, %2};" : "=l"(r) : "r"(__float_as_uint(lo)), "r"(__float_as_uint(hi)));
    return r;
}

__device__ __forceinline__ void unpack2(unsigned long long v, float& lo, float& hi) {
    unsigned int a, b;
    asm("mov.b64 {%0, %1}, %2;" : "=r"(a), "=r"(b) : "l"(v));
    lo = __uint_as_float(a);
    hi = __uint_as_float(b);
}

__global__ void __launch_bounds__(256, 3)
dice_fused_kernel(const float* __restrict__ bv,
                  const float* __restrict__ Qm,    // [10,10]
                  const float* __restrict__ W,     // [1024,10]
                  const float* __restrict__ bias,  // [1024]
                  float* __restrict__ out,
                  int N) {
    // polar values duplicated into both f32x2 lanes, [row][d]
    __shared__ __align__(16) unsigned long long spolar[RPB][DPOL];
    __shared__ float sQ[DPOL * DPOL];

    const int t = threadIdx.x;
    const int rowBase = blockIdx.x * RPB;

    // issue the bv load FIRST — its DRAM latency hides under the barrier
    // and the 400-FMA fold below
    const int rr = rowBase + t;
    float v = (rr < N) ? bv[rr] : 0.f;

    // stage Q for broadcast
    if (t < DPOL * DPOL) sQ[t] = Qm[t];
    __syncthreads();   // sQ ready

    // ---- fold WQ for this thread's 4 output columns (no spolar dep) ----
    const int c0 = t * 4;
    unsigned long long wqa[DPOL], wqb[DPOL];
    {
        float d0[DPOL], d1[DPOL];
#pragma unroll
        for (int d = 0; d < DPOL; d++) { d0[d] = 0.f; d1[d] = 0.f; }
#pragma unroll
        for (int k = 0; k < DPOL; k++) {
            float w0 = W[(c0 + 0) * DPOL + k];
            float w1 = W[(c0 + 1) * DPOL + k];
#pragma unroll
            for (int d = 0; d < DPOL; d++) {
                float q = sQ[k * DPOL + d];
                d0[d] = fmaf(w0, q, d0[d]);
                d1[d] = fmaf(w1, q, d1[d]);
            }
        }
#pragma unroll
        for (int d = 0; d < DPOL; d++) wqa[d] = pack2(d0[d], d1[d]);
#pragma unroll
        for (int d = 0; d < DPOL; d++) { d0[d] = 0.f; d1[d] = 0.f; }
#pragma unroll
        for (int k = 0; k < DPOL; k++) {
            float w2 = W[(c0 + 2) * DPOL + k];
            float w3 = W[(c0 + 3) * DPOL + k];
#pragma unroll
            for (int d = 0; d < DPOL; d++) {
                float q = sQ[k * DPOL + d];
                d0[d] = fmaf(w2, q, d0[d]);
                d1[d] = fmaf(w3, q, d1[d]);
            }
        }
#pragma unroll
        for (int d = 0; d < DPOL; d++) wqb[d] = pack2(d0[d], d1[d]);
    }

    // ---- phase 1: polar for this thread's row (v already resident) ----
    {
        const float k = (float)(CUDART_PI / 85.0);
        float theta = __logf(0.01f + fabsf(v)) * k;
        float s, c;
        __sincosf(theta, &s, &c);
        float p = c;
#pragma unroll
        for (int j = 0; j < 9; j++) {
            spolar[t][j] = pack_dup(p);
            p *= s;
        }
        float s2 = s * s;
        float s4 = s2 * s2;
        float s8 = s4 * s4;
        spolar[t][9] = pack_dup(s8 * s2);   // polar[9] = s^10
    }

    ulonglong2 b2 = *reinterpret_cast<const ulonglong2*>(&bias[c0]);
    const unsigned long long ba = b2.x, bb = b2.y;

    __syncthreads();   // spolar ready

    const int nr = min(RPB, N - rowBase);

    // ---- phase 2: each row, every thread emits 4 contiguous fp32 outputs.
    //      All 5 spolar chunks loaded at loop top for MLP (R4 pattern). ----
    for (int r = 0; r < nr; r++) {
        const ulonglong2* sp = reinterpret_cast<const ulonglong2*>(&spolar[r][0]);
        ulonglong2 q0 = sp[0];  // d0,d1
        ulonglong2 q1 = sp[1];  // d2,d3
        ulonglong2 q2 = sp[2];  // d4,d5
        ulonglong2 q3 = sp[3];  // d6,d7
        ulonglong2 q4 = sp[4];  // d8,d9

        unsigned long long a = ba, b = bb;
        a = fma2(q0.x, wqa[0], a);  b = fma2(q0.x, wqb[0], b);
        a = fma2(q0.y, wqa[1], a);  b = fma2(q0.y, wqb[1], b);
        a = fma2(q1.x, wqa[2], a);  b = fma2(q1.x, wqb[2], b);
        a = fma2(q1.y, wqa[3], a);  b = fma2(q1.y, wqb[3], b);
        a = fma2(q2.x, wqa[4], a);  b = fma2(q2.x, wqb[4], b);
        a = fma2(q2.y, wqa[5], a);  b = fma2(q2.y, wqb[5], b);
        a = fma2(q3.x, wqa[6], a);  b = fma2(q3.x, wqb[6], b);
        a = fma2(q3.y, wqa[7], a);  b = fma2(q3.y, wqb[7], b);
        a = fma2(q4.x, wqa[8], a);  b = fma2(q4.x, wqb[8], b);
        a = fma2(q4.y, wqa[9], a);  b = fma2(q4.y, wqb[9], b);

        float4 o;
        unpack2(a, o.x, o.y);
        unpack2(b, o.z, o.w);
        reinterpret_cast<float4*>(out)[(size_t)(rowBase + r) * (EMB / 4) + t] = o;
    }
}

extern "C" void kernel_launch(void* const* d_in, const int* in_sizes, int n_in,
                              void* d_out, int out_size) {
    const float* bv = (const float*)d_in[0];   // [N]
    const float* Q  = (const float*)d_in[1];   // [10,10]
    const float* W  = (const float*)d_in[2];   // [1024,10]
    const float* b  = (const float*)d_in[3];   // [1024]
    float* out = (float*)d_out;
    const int N = in_sizes[0];

    int nblocks = (N + RPB - 1) / RPB;
    dice_fused_kernel<<<nblocks, 256>>>(bv, Q, W, b, out, N);
}

// round 7
// speedup vs baseline: 1.0132x; 1.0126x over previous
#include <cuda_runtime.h>
#include <math_constants.h>

// DiceEmbedding fused single kernel:
//   out[n,e] = sum_d polar(v_n)[d] * (W@Q)[e,d] + b[e]
//   theta = log(0.01+|v|)/85*pi ; s=sin, c=cos
//   polar[j] = s^j * c (j=0..8), polar[9] = s^10
//
// R7: exact R4 structure (best measured: kernel 154.8us) with the phase-2
// loop unrolled x2 on the full-tile path: 2 independent STG.128 in flight
// per iteration for deeper store pipelining into the L2 write drain.

#define EMB 1024
#define DPOL 10
#define RPB 256   // rows per block

__device__ __forceinline__ unsigned long long fma2(unsigned long long a,
                                                   unsigned long long b,
                                                   unsigned long long c) {
    unsigned long long d;
    asm("fma.rn.f32x2 %0, %1, %2, %3;" : "=l"(d) : "l"(a), "l"(b), "l"(c));
    return d;
}

__device__ __forceinline__ unsigned long long pack_dup(float x) {
    unsigned long long r;
    unsigned int u = __float_as_uint(x);
    asm("mov.b64 %0, {%1, %1};" : "=l"(r) : "r"(u));
    return r;
}

__device__ __forceinline__ unsigned long long pack2(float lo, float hi) {
    unsigned long long r;
    asm("mov.b64 %0, {%1, %2};" : "=l"(r) : "r"(__float_as_uint(lo)), "r"(__float_as_uint(hi)));
    return r;
}

__device__ __forceinline__ void unpack2(unsigned long long v, float& lo, float& hi) {
    unsigned int a, b;
    asm("mov.b64 {%0, %1}, %2;" : "=r"(a), "=r"(b) : "l"(v));
    lo = __uint_as_float(a);
    hi = __uint_as_float(b);
}

__global__ void __launch_bounds__(256, 3)
dice_fused_kernel(const float* __restrict__ bv,
                  const float* __restrict__ Qm,    // [10,10]
                  const float* __restrict__ W,     // [1024,10]
                  const float* __restrict__ bias,  // [1024]
                  float* __restrict__ out,
                  int N) {
    // polar values duplicated into both f32x2 lanes, [row][d]
    __shared__ __align__(16) unsigned long long spolar[RPB][DPOL];
    __shared__ float sQ[DPOL * DPOL];

    const int t = threadIdx.x;
    const int rowBase = blockIdx.x * RPB;

    // stage Q for broadcast
    if (t < DPOL * DPOL) sQ[t] = Qm[t];
    __syncthreads();   // sQ ready

    // ---- phase 1: each thread computes polar for one row, writes smem ----
    {
        int r = rowBase + t;
        float v = (r < N) ? bv[r] : 0.f;
        const float k = (float)(CUDART_PI / 85.0);
        float theta = __logf(0.01f + fabsf(v)) * k;
        float s, c;
        __sincosf(theta, &s, &c);
        float p = c;
#pragma unroll
        for (int j = 0; j < 9; j++) {
            spolar[t][j] = pack_dup(p);
            p *= s;
        }
        float s2 = s * s;
        float s4 = s2 * s2;
        float s8 = s4 * s4;
        spolar[t][9] = pack_dup(s8 * s2);   // polar[9] = s^10
    }

    // ---- fold WQ for this thread's 4 output columns (independent of
    //      spolar; overlaps other warps reaching the barrier) ----
    const int c0 = t * 4;
    unsigned long long wqa[DPOL], wqb[DPOL];
    {
        float d0[DPOL], d1[DPOL];
#pragma unroll
        for (int d = 0; d < DPOL; d++) { d0[d] = 0.f; d1[d] = 0.f; }
#pragma unroll
        for (int k = 0; k < DPOL; k++) {
            float w0 = W[(c0 + 0) * DPOL + k];
            float w1 = W[(c0 + 1) * DPOL + k];
#pragma unroll
            for (int d = 0; d < DPOL; d++) {
                float q = sQ[k * DPOL + d];
                d0[d] = fmaf(w0, q, d0[d]);
                d1[d] = fmaf(w1, q, d1[d]);
            }
        }
#pragma unroll
        for (int d = 0; d < DPOL; d++) wqa[d] = pack2(d0[d], d1[d]);
#pragma unroll
        for (int d = 0; d < DPOL; d++) { d0[d] = 0.f; d1[d] = 0.f; }
#pragma unroll
        for (int k = 0; k < DPOL; k++) {
            float w2 = W[(c0 + 2) * DPOL + k];
            float w3 = W[(c0 + 3) * DPOL + k];
#pragma unroll
            for (int d = 0; d < DPOL; d++) {
                float q = sQ[k * DPOL + d];
                d0[d] = fmaf(w2, q, d0[d]);
                d1[d] = fmaf(w3, q, d1[d]);
            }
        }
#pragma unroll
        for (int d = 0; d < DPOL; d++) wqb[d] = pack2(d0[d], d1[d]);
    }

    ulonglong2 b2 = *reinterpret_cast<const ulonglong2*>(&bias[c0]);
    const unsigned long long ba = b2.x, bb = b2.y;

    __syncthreads();   // spolar ready

    const int nr = min(RPB, N - rowBase);
    float4* outp = reinterpret_cast<float4*>(out) + (size_t)rowBase * (EMB / 4) + t;

#define ROW_BODY(RI, OUTP)                                                    \
    {                                                                         \
        const ulonglong2* sp =                                                \
            reinterpret_cast<const ulonglong2*>(&spolar[(RI)][0]);            \
        ulonglong2 q0 = sp[0];                                                \
        ulonglong2 q1 = sp[1];                                                \
        ulonglong2 q2 = sp[2];                                                \
        ulonglong2 q3 = sp[3];                                                \
        ulonglong2 q4 = sp[4];                                                \
        unsigned long long a = ba, b = bb;                                    \
        a = fma2(q0.x, wqa[0], a);  b = fma2(q0.x, wqb[0], b);                \
        a = fma2(q0.y, wqa[1], a);  b = fma2(q0.y, wqb[1], b);                \
        a = fma2(q1.x, wqa[2], a);  b = fma2(q1.x, wqb[2], b);                \
        a = fma2(q1.y, wqa[3], a);  b = fma2(q1.y, wqb[3], b);                \
        a = fma2(q2.x, wqa[4], a);  b = fma2(q2.x, wqb[4], b);                \
        a = fma2(q2.y, wqa[5], a);  b = fma2(q2.y, wqb[5], b);                \
        a = fma2(q3.x, wqa[6], a);  b = fma2(q3.x, wqb[6], b);                \
        a = fma2(q3.y, wqa[7], a);  b = fma2(q3.y, wqb[7], b);                \
        a = fma2(q4.x, wqa[8], a);  b = fma2(q4.x, wqb[8], b);                \
        a = fma2(q4.y, wqa[9], a);  b = fma2(q4.y, wqb[9], b);                \
        float4 o;                                                             \
        unpack2(a, o.x, o.y);                                                 \
        unpack2(b, o.z, o.w);                                                 \
        *(OUTP) = o;                                                          \
    }

    if (nr == RPB) {
        // full tile: constant trip count, unroll x2 for 2 stores in flight
        for (int r = 0; r < RPB; r += 2) {
            ROW_BODY(r,     outp);
            ROW_BODY(r + 1, outp + (EMB / 4));
            outp += 2 * (EMB / 4);
        }
    } else {
        for (int r = 0; r < nr; r++) {
            ROW_BODY(r, outp);
            outp += EMB / 4;
        }
    }
#undef ROW_BODY
}

extern "C" void kernel_launch(void* const* d_in, const int* in_sizes, int n_in,
                              void* d_out, int out_size) {
    const float* bv = (const float*)d_in[0];   // [N]
    const float* Q  = (const float*)d_in[1];   // [10,10]
    const float* W  = (const float*)d_in[2];   // [1024,10]
    const float* b  = (const float*)d_in[3];   // [1024]
    float* out = (float*)d_out;
    const int N = in_sizes[0];

    int nblocks = (N + RPB - 1) / RPB;
    dice_fused_kernel<<<nblocks, 256>>>(bv, Q, W, b, out, N);
}